// round 9
// baseline (speedup 1.0000x reference)
#include <cuda_runtime.h>
#include <cuda_bf16.h>

// SingleRoIExtractor: FPN RoIAlign (aligned=False), out 7x7, sr=2.
// R8: sample-outer transient geometry, 8 channels per thread ->
// 32 independent LDGs per sample iteration, geometry ALU amortized 8x.

#define OUTS   7
#define CH     256
#define BINS   (OUTS * OUTS)            // 49
#define PER_ROI (CH * BINS)             // 12544
#define CPT    8                        // channels per thread
#define CGRP   (CH / CPT)               // 32
#define THR_PER_ROI (CGRP * BINS)       // 1568
#define BLK    224
#define BLOCKS_PER_ROI (THR_PER_ROI / BLK)   // 7

__global__ void __launch_bounds__(BLK, 6)
roi_extract_kernel(const float* __restrict__ f0,
                   const float* __restrict__ f1,
                   const float* __restrict__ f2,
                   const float* __restrict__ f3,
                   const float* __restrict__ rois,
                   float* __restrict__ out)
{
    const int n     = blockIdx.x / BLOCKS_PER_ROI;
    const int blk   = blockIdx.x % BLOCKS_PER_ROI;
    const int local = blk * BLK + threadIdx.x;      // [0, 1568)
    const int c0    = local / BINS;                 // [0, 32)
    const int bin   = local - c0 * BINS;            // [0, 49)
    const int ph    = bin / OUTS;
    const int pw    = bin - ph * OUTS;

    // ---- per-RoI params ----
    const float rb  = __ldg(rois + n * 5 + 0);
    const float rx1 = __ldg(rois + n * 5 + 1);
    const float ry1 = __ldg(rois + n * 5 + 2);
    const float rx2 = __ldg(rois + n * 5 + 3);
    const float ry2 = __ldg(rois + n * 5 + 4);

    const float sc = sqrtf((rx2 - rx1 + 1.0f) * (ry2 - ry1 + 1.0f));
    int lvl = (int)floorf(log2f(sc * (1.0f / 56.0f) + 1e-6f));
    lvl = lvl < 0 ? 0 : (lvl > 3 ? 3 : lvl);

    const float* f; int H, W; float ss;
    if      (lvl == 0) { f = f0; H = 200; W = 304; ss = 0.25f;    }
    else if (lvl == 1) { f = f1; H = 100; W = 152; ss = 0.125f;   }
    else if (lvl == 2) { f = f2; H = 50;  W = 76;  ss = 0.0625f;  }
    else               { f = f3; H = 25;  W = 38;  ss = 0.03125f; }

    const int   b    = (int)rb;
    const int   HW   = H * W;
    const float x1   = rx1 * ss, y1 = ry1 * ss;
    const float binw = fmaxf(rx2 * ss - x1, 1.0f) * (1.0f / OUTS);
    const float binh = fmaxf(ry2 * ss - y1, 1.0f) * (1.0f / OUTS);
    const float Hf = (float)H, Wf = (float)W;

    const float* __restrict__ fc0 = f + (size_t)b * CH * HW + (size_t)c0 * HW;
    const size_t cstep = (size_t)CGRP * HW;          // 32 channel planes

    float acc[CPT];
    #pragma unroll
    for (int j = 0; j < CPT; ++j) acc[j] = 0.0f;

    // sample-outer, NOT unrolled: geometry regs are transient per iteration
    #pragma unroll 1
    for (int s = 0; s < 4; ++s) {
        const int iy = s >> 1, ix = s & 1;
        const float y = y1 + ((float)(ph * 2 + iy) + 0.5f) * 0.5f * binh;
        const float x = x1 + ((float)(pw * 2 + ix) + 0.5f) * 0.5f * binw;
        const bool valid = (y >= -1.0f) & (y <= Hf) & (x >= -1.0f) & (x <= Wf);

        const float yc = fminf(fmaxf(y, 0.0f), Hf - 1.0f);
        const float xc = fminf(fmaxf(x, 0.0f), Wf - 1.0f);
        const int   yi = (int)yc;
        const int   xi = (int)xc;
        const float ly = yc - (float)yi;
        const float lx = xc - (float)xi;
        const int   yB = min(yi + 1, H - 1);
        const int   xB = min(xi + 1, W - 1);

        const float vmul = valid ? 0.25f : 0.0f;   // fold 1/4 sample mean
        const float wy0 = (1.0f - ly) * vmul;
        const float wy1 = ly * vmul;
        const float w00 = wy0 * (1.0f - lx);
        const float w01 = wy0 * lx;
        const float w10 = wy1 * (1.0f - lx);
        const float w11 = wy1 * lx;

        const int o00 = yi * W + xi, o01 = yi * W + xB;
        const int o10 = yB * W + xi, o11 = yB * W + xB;

        // 32 independent LDGs (4 taps x 8 channel planes)
        #pragma unroll
        for (int j = 0; j < CPT; ++j) {
            const float* __restrict__ fp = fc0 + j * cstep;
            acc[j] += __ldg(fp + o00) * w00 + __ldg(fp + o01) * w01
                    + __ldg(fp + o10) * w10 + __ldg(fp + o11) * w11;
        }
    }

    float* __restrict__ po = out + (size_t)n * PER_ROI + (size_t)c0 * BINS + bin;
    const size_t ostep = (size_t)CGRP * BINS;       // 1568
    #pragma unroll
    for (int j = 0; j < CPT; ++j)
        __stcs(po + j * ostep, acc[j]);
}

extern "C" void kernel_launch(void* const* d_in, const int* in_sizes, int n_in,
                              void* d_out, int out_size)
{
    const float* f0   = (const float*)d_in[0];
    const float* f1   = (const float*)d_in[1];
    const float* f2   = (const float*)d_in[2];
    const float* f3   = (const float*)d_in[3];
    const float* rois = (const float*)d_in[4];
    float* out = (float*)d_out;

    const int K = in_sizes[4] / 5;
    roi_extract_kernel<<<K * BLOCKS_PER_ROI, BLK>>>(f0, f1, f2, f3, rois, out);
}

// round 12
// speedup vs baseline: 1.3825x; 1.3825x over previous
#include <cuda_runtime.h>
#include <cuda_bf16.h>

// SingleRoIExtractor: FPN RoIAlign (aligned=False), out 7x7, sr=2.
// R9: lane packing (bin, sample) -> warp tap footprint ~8 bins x 3 rows
// (compact, few L1 lines per LDG). Thread = one sample x 8 channels;
// 4-lane shfl reduce across samples; lane s==0 stores 8 outputs.

#define OUTS   7
#define CH     256
#define BINS   (OUTS * OUTS)          // 49
#define PER_ROI (CH * BINS)           // 12544
#define CPT    8                      // channels per thread
#define NCG    (CH / CPT)             // 32 channel-groups per RoI
#define ACTIVE (BINS * 4)             // 196 active threads per block
#define BLK    224

__global__ void __launch_bounds__(BLK, 8)
roi_extract_kernel(const float* __restrict__ f0,
                   const float* __restrict__ f1,
                   const float* __restrict__ f2,
                   const float* __restrict__ f3,
                   const float* __restrict__ rois,
                   float* __restrict__ out)
{
    const int t = threadIdx.x;
    if (t >= ACTIVE) return;

    const int n  = blockIdx.x / NCG;    // roi
    const int cg = blockIdx.x % NCG;    // channel group (8 channels)

    const int bin = t >> 2;             // warp = 8 consecutive bins
    const int s   = t & 3;              // sample within bin
    const int ph  = bin / OUTS;
    const int pw  = bin - ph * OUTS;
    const int iy  = s >> 1;
    const int ix  = s & 1;

    // ---- per-RoI params (redundant per thread; trivial cost) ----
    const float rb  = __ldg(rois + n * 5 + 0);
    const float rx1 = __ldg(rois + n * 5 + 1);
    const float ry1 = __ldg(rois + n * 5 + 2);
    const float rx2 = __ldg(rois + n * 5 + 3);
    const float ry2 = __ldg(rois + n * 5 + 4);

    const float sc = sqrtf((rx2 - rx1 + 1.0f) * (ry2 - ry1 + 1.0f));
    int lvl = (int)floorf(log2f(sc * (1.0f / 56.0f) + 1e-6f));
    lvl = lvl < 0 ? 0 : (lvl > 3 ? 3 : lvl);

    const float* f; int H, W; float ss;
    if      (lvl == 0) { f = f0; H = 200; W = 304; ss = 0.25f;    }
    else if (lvl == 1) { f = f1; H = 100; W = 152; ss = 0.125f;   }
    else if (lvl == 2) { f = f2; H = 50;  W = 76;  ss = 0.0625f;  }
    else               { f = f3; H = 25;  W = 38;  ss = 0.03125f; }

    const int   b    = (int)rb;
    const int   HW   = H * W;
    const float x1   = rx1 * ss, y1 = ry1 * ss;
    const float binw = fmaxf(rx2 * ss - x1, 1.0f) * (1.0f / OUTS);
    const float binh = fmaxf(ry2 * ss - y1, 1.0f) * (1.0f / OUTS);
    const float Hf = (float)H, Wf = (float)W;

    // ---- geometry for this thread's single sample ----
    const float y = y1 + ((float)(ph * 2 + iy) + 0.5f) * 0.5f * binh;
    const float x = x1 + ((float)(pw * 2 + ix) + 0.5f) * 0.5f * binw;
    const bool valid = (y >= -1.0f) & (y <= Hf) & (x >= -1.0f) & (x <= Wf);

    const float yc = fminf(fmaxf(y, 0.0f), Hf - 1.0f);
    const float xc = fminf(fmaxf(x, 0.0f), Wf - 1.0f);
    const int   yi = (int)yc;
    const int   xi = (int)xc;
    const float ly = yc - (float)yi;
    const float lx = xc - (float)xi;
    const int   yB = min(yi + 1, H - 1);
    const int   xB = min(xi + 1, W - 1);

    const float vmul = valid ? 0.25f : 0.0f;       // fold 1/4 sample mean
    const float wy0 = (1.0f - ly) * vmul;
    const float wy1 = ly * vmul;
    const float w00 = wy0 * (1.0f - lx);
    const float w01 = wy0 * lx;
    const float w10 = wy1 * (1.0f - lx);
    const float w11 = wy1 * lx;

    const int o00 = yi * W + xi, o01 = yi * W + xB;
    const int o10 = yB * W + xi, o11 = yB * W + xB;

    // ---- 8 contiguous channels: 32 independent LDGs ----
    const float* __restrict__ base =
        f + (size_t)(b * CH + cg * CPT) * HW;

    float acc[CPT];
    #pragma unroll
    for (int j = 0; j < CPT; ++j) {
        const float* __restrict__ fp = base + (size_t)j * HW;
        acc[j] = __ldg(fp + o00) * w00 + __ldg(fp + o01) * w01
               + __ldg(fp + o10) * w10 + __ldg(fp + o11) * w11;
    }

    // ---- reduce the 4 sample-lanes (groups of 4, warp-aligned) ----
    const int lane = t & 31;
    const unsigned gmask = 0xFu << (lane & ~3);
    #pragma unroll
    for (int j = 0; j < CPT; ++j) {
        acc[j] += __shfl_xor_sync(gmask, acc[j], 1);
        acc[j] += __shfl_xor_sync(gmask, acc[j], 2);
    }

    if (s == 0) {
        float* __restrict__ po =
            out + (size_t)n * PER_ROI + (size_t)(cg * CPT) * BINS + bin;
        #pragma unroll
        for (int j = 0; j < CPT; ++j)
            __stcs(po + j * BINS, acc[j]);
    }
}

extern "C" void kernel_launch(void* const* d_in, const int* in_sizes, int n_in,
                              void* d_out, int out_size)
{
    const float* f0   = (const float*)d_in[0];
    const float* f1   = (const float*)d_in[1];
    const float* f2   = (const float*)d_in[2];
    const float* f3   = (const float*)d_in[3];
    const float* rois = (const float*)d_in[4];
    float* out = (float*)d_out;

    const int K = in_sizes[4] / 5;
    roi_extract_kernel<<<K * NCG, BLK>>>(f0, f1, f2, f3, rois, out);
}

// round 13
// speedup vs baseline: 1.4416x; 1.0427x over previous
#include <cuda_runtime.h>
#include <cuda_bf16.h>

// SingleRoIExtractor: FPN RoIAlign (aligned=False), out 7x7, sr=2.
// R12: R6 compute kernel (best: 121.6us) + RoI order sorted by (level,batch)
// so concurrent blocks share one feature map (<=62MB, fits 126MB L2).

#define OUTS   7
#define CH     256
#define BINS   (OUTS * OUTS)            // 49
#define PER_ROI (CH * BINS)             // 12544
#define CPT    4                        // channels per thread
#define CGRP   (CH / CPT)               // 64
#define THR_PER_ROI (CGRP * BINS)       // 3136
#define BLK    224
#define BLOCKS_PER_ROI (THR_PER_ROI / BLK)   // 14
#define MAXK   4096

__device__ int g_order[MAXK];

__device__ __forceinline__ int roi_level(float rx1, float ry1, float rx2, float ry2)
{
    const float sc = sqrtf((rx2 - rx1 + 1.0f) * (ry2 - ry1 + 1.0f));
    int lvl = (int)floorf(log2f(sc * (1.0f / 56.0f) + 1e-6f));
    return lvl < 0 ? 0 : (lvl > 3 ? 3 : lvl);
}

// One block: counting sort of RoI indices by key = lvl*2 + batch (8 buckets).
__global__ void sort_rois_kernel(const float* __restrict__ rois, int K)
{
    __shared__ int cnt[8];
    __shared__ int base[8];
    const int t = threadIdx.x;
    if (t < 8) cnt[t] = 0;
    __syncthreads();

    int key[(MAXK + 1023) / 1024];
    for (int i = t, q = 0; i < K; i += 1024, ++q) {
        const int   b   = (int)rois[i * 5 + 0];
        const int   lvl = roi_level(rois[i * 5 + 1], rois[i * 5 + 2],
                                    rois[i * 5 + 3], rois[i * 5 + 4]);
        key[q] = lvl * 2 + b;
        atomicAdd(&cnt[key[q]], 1);
    }
    __syncthreads();
    if (t == 0) {
        int s = 0;
        #pragma unroll
        for (int i = 0; i < 8; ++i) { base[i] = s; s += cnt[i]; }
    }
    __syncthreads();
    for (int i = t, q = 0; i < K; i += 1024, ++q) {
        const int pos = atomicAdd(&base[key[q]], 1);
        g_order[pos] = i;
    }
}

__global__ void __launch_bounds__(BLK)
roi_extract_kernel(const float* __restrict__ f0,
                   const float* __restrict__ f1,
                   const float* __restrict__ f2,
                   const float* __restrict__ f3,
                   const float* __restrict__ rois,
                   float* __restrict__ out)
{
    const int n     = g_order[blockIdx.x / BLOCKS_PER_ROI];
    const int blk   = blockIdx.x % BLOCKS_PER_ROI;
    const int local = blk * BLK + threadIdx.x;      // [0, 3136)
    const int c0    = local / BINS;                 // [0, 64)
    const int bin   = local - c0 * BINS;            // [0, 49)
    const int ph    = bin / OUTS;
    const int pw    = bin - ph * OUTS;

    // ---- per-RoI params ----
    const float rb  = __ldg(rois + n * 5 + 0);
    const float rx1 = __ldg(rois + n * 5 + 1);
    const float ry1 = __ldg(rois + n * 5 + 2);
    const float rx2 = __ldg(rois + n * 5 + 3);
    const float ry2 = __ldg(rois + n * 5 + 4);

    const int lvl = roi_level(rx1, ry1, rx2, ry2);

    const float* f; int H, W; float ss;
    if      (lvl == 0) { f = f0; H = 200; W = 304; ss = 0.25f;    }
    else if (lvl == 1) { f = f1; H = 100; W = 152; ss = 0.125f;   }
    else if (lvl == 2) { f = f2; H = 50;  W = 76;  ss = 0.0625f;  }
    else               { f = f3; H = 25;  W = 38;  ss = 0.03125f; }

    const int   b    = (int)rb;
    const int   HW   = H * W;
    const float x1   = rx1 * ss, y1 = ry1 * ss;
    const float binw = fmaxf(rx2 * ss - x1, 1.0f) * (1.0f / OUTS);
    const float binh = fmaxf(ry2 * ss - y1, 1.0f) * (1.0f / OUTS);
    const float Hf = (float)H, Wf = (float)W;

    // ---- geometry for the 4 samples of this bin, once, in registers ----
    int   o00[4], o01[4], o10[4], o11[4];
    float w00[4], w01[4], w10[4], w11[4];

    #pragma unroll
    for (int s = 0; s < 4; ++s) {
        const int iy = s >> 1, ix = s & 1;
        const float y = y1 + ((float)(ph * 2 + iy) + 0.5f) * 0.5f * binh;
        const float x = x1 + ((float)(pw * 2 + ix) + 0.5f) * 0.5f * binw;
        const bool valid = (y >= -1.0f) & (y <= Hf) & (x >= -1.0f) & (x <= Wf);

        const float yc = fminf(fmaxf(y, 0.0f), Hf - 1.0f);
        const float xc = fminf(fmaxf(x, 0.0f), Wf - 1.0f);
        const int   yi = (int)yc;
        const int   xi = (int)xc;
        const float ly = yc - (float)yi;
        const float lx = xc - (float)xi;
        const int   yB = min(yi + 1, H - 1);
        const int   xB = min(xi + 1, W - 1);

        const float vmul = valid ? 0.25f : 0.0f;    // fold 1/4 sample mean
        const float wy0 = (1.0f - ly) * vmul;
        const float wy1 = ly * vmul;

        o00[s] = yi * W + xi;  o01[s] = yi * W + xB;
        o10[s] = yB * W + xi;  o11[s] = yB * W + xB;
        w00[s] = wy0 * (1.0f - lx);  w01[s] = wy0 * lx;
        w10[s] = wy1 * (1.0f - lx);  w11[s] = wy1 * lx;
    }

    // ---- 4 channels per thread: pure LDG + FFMA + STG ----
    const float* __restrict__ base = f + (size_t)b * CH * HW + (size_t)c0 * HW;
    float* __restrict__ po = out + (size_t)n * PER_ROI + (size_t)c0 * BINS + bin;
    const size_t cstep = (size_t)CGRP * HW;          // 64 channel planes
    const size_t ostep = (size_t)CGRP * BINS;

    #pragma unroll
    for (int j = 0; j < CPT; ++j) {
        const float* __restrict__ fc = base + j * cstep;
        float acc = 0.0f;
        #pragma unroll
        for (int s = 0; s < 4; ++s) {
            acc += __ldg(fc + o00[s]) * w00[s]
                 + __ldg(fc + o01[s]) * w01[s]
                 + __ldg(fc + o10[s]) * w10[s]
                 + __ldg(fc + o11[s]) * w11[s];
        }
        __stcs(po + j * ostep, acc);
    }
}

extern "C" void kernel_launch(void* const* d_in, const int* in_sizes, int n_in,
                              void* d_out, int out_size)
{
    const float* f0   = (const float*)d_in[0];
    const float* f1   = (const float*)d_in[1];
    const float* f2   = (const float*)d_in[2];
    const float* f3   = (const float*)d_in[3];
    const float* rois = (const float*)d_in[4];
    float* out = (float*)d_out;

    const int K = in_sizes[4] / 5;
    sort_rois_kernel<<<1, 1024>>>(rois, K);
    roi_extract_kernel<<<K * BLOCKS_PER_ROI, BLK>>>(f0, f1, f2, f3, rois, out);
}